// round 13
// baseline (speedup 1.0000x reference)
#include <cuda_runtime.h>
#include <cstdint>
#include <cstddef>

#define SEQ    512
#define BATCH  64
#define INDIM  128
#define HDIM   512

#define CL     8             // CTAs per cluster (H split)
#define NCLUST 8             // clusters; each serves 8 batch rows
#define NGR    4             // interleaved groups per cluster
#define GR     2             // rows per group (4*2 = 8 rows)
#define JC     (HDIM / CL)   // 64 j columns per CTA
#define NCW    8             // compute warps
#define RT     (NCW * 32 + 32)   // 288: 8 compute + 1 comm warp

typedef unsigned long long u64;

__device__ __forceinline__ u64 fma2(u64 a, u64 b, u64 c) {
    u64 d;
    asm("fma.rn.f32x2 %0, %1, %2, %3;" : "=l"(d) : "l"(a), "l"(b), "l"(c));
    return d;
}
__device__ __forceinline__ uint32_t smem_u32(const void* p) {
    uint32_t a;
    asm("{ .reg .u64 t; cvta.to.shared.u64 t, %1; cvt.u32.u64 %0, t; }" : "=r"(a) : "l"(p));
    return a;
}
__device__ __forceinline__ uint32_t mapa_u32(uint32_t a, uint32_t r) {
    uint32_t d;
    asm("mapa.shared::cluster.u32 %0, %1, %2;" : "=r"(d) : "r"(a), "r"(r));
    return d;
}
__device__ __forceinline__ void mbar_init(uint32_t a, uint32_t cnt) {
    asm volatile("mbarrier.init.shared.b64 [%0], %1;" :: "r"(a), "r"(cnt) : "memory");
}
__device__ __forceinline__ void mbar_wait_cluster(uint32_t a, uint32_t parity) {
    asm volatile(
        "{\n\t"
        ".reg .pred P;\n\t"
        "WL_%=:\n\t"
        "mbarrier.try_wait.parity.acquire.cluster.shared::cta.b64 P, [%0], %1, 0x989680;\n\t"
        "@P bra.uni WD_%=;\n\t"
        "bra.uni WL_%=;\n\t"
        "WD_%=:\n\t"
        "}"
        :: "r"(a), "r"(parity) : "memory");
}
__device__ __forceinline__ void mbar_arrive_remote(uint32_t a) {
    asm volatile("mbarrier.arrive.release.cluster.shared::cluster.b64 _, [%0];"
                 :: "r"(a) : "memory");
}
__device__ __forceinline__ void fence_cluster() {
    asm volatile("fence.acq_rel.cluster;" ::: "memory");
}
__device__ __forceinline__ void st_cluster_b64(uint32_t a, u64 v) {
    asm volatile("st.shared::cluster.b64 [%0], %1;" :: "r"(a), "l"(v) : "memory");
}
__device__ __forceinline__ void nbar_arrive(int id) {   // non-blocking
    asm volatile("bar.arrive %0, %1;" :: "r"(id), "r"(RT) : "memory");
}
__device__ __forceinline__ void nbar_sync(int id) {     // blocking (comm warp)
    asm volatile("bar.sync %0, %1;" :: "r"(id), "r"(RT) : "memory");
}
#define CLUSTER_SYNC() do { \
    asm volatile("barrier.cluster.arrive.aligned;" ::: "memory"); \
    asm volatile("barrier.cluster.wait.aligned;"   ::: "memory"); \
} while (0)

// ---------------------------------------------------------------------------
// xi kernel (validated R3-R12): out[s][b][h] = x.Wi + bi + bh
// ---------------------------------------------------------------------------
__global__ __launch_bounds__(256) void xi_kernel(
    const float* __restrict__ x, const float* __restrict__ Wi,
    const float* __restrict__ bi, const float* __restrict__ bh,
    float* __restrict__ out)
{
    extern __shared__ float sm[];
    float* ws = sm;               // [128][130]
    float* xs = sm + 128 * 130;   // [64][130]

    const int tid = threadIdx.x;
    const int sb0 = blockIdx.x * 64;
    const int h0  = blockIdx.y * 128;

    for (int i = tid; i < 128 * INDIM; i += 256) {
        int r = i >> 7, k = i & 127;
        ws[r * 130 + k] = Wi[(h0 + r) * INDIM + k];
    }
    for (int i = tid; i < 64 * INDIM; i += 256) {
        int r = i >> 7, k = i & 127;
        xs[r * 130 + k] = x[(size_t)(sb0 + r) * INDIM + k];
    }
    __syncthreads();

    const int w  = tid >> 5;
    const int tx = tid & 31;

    u64 acc2[8][4];
#pragma unroll
    for (int i = 0; i < 8; i++)
#pragma unroll
        for (int j = 0; j < 4; j++) acc2[i][j] = 0ull;

    const u64* xb2 = (const u64*)xs + (w * 8) * 65;
    const u64* wb2 = (const u64*)ws;

#pragma unroll 4
    for (int kp = 0; kp < 64; kp++) {
        u64 xv[8], wv[4];
#pragma unroll
        for (int i = 0; i < 8; i++) xv[i] = xb2[i * 65 + kp];
#pragma unroll
        for (int j = 0; j < 4; j++) wv[j] = wb2[(j * 32 + tx) * 65 + kp];
#pragma unroll
        for (int i = 0; i < 8; i++)
#pragma unroll
            for (int j = 0; j < 4; j++) acc2[i][j] = fma2(xv[i], wv[j], acc2[i][j]);
    }

#pragma unroll
    for (int j = 0; j < 4; j++) {
        int h = h0 + j * 32 + tx;
        float b = bi[h] + bh[h];
#pragma unroll
        for (int i = 0; i < 8; i++) {
            float2 a = *reinterpret_cast<float2*>(&acc2[i][j]);
            out[(size_t)(sb0 + w * 8 + i) * HDIM + h] = a.x + a.y + b;
        }
    }
}

// ---------------------------------------------------------------------------
// Recurrence: 8 clusters x 8 CTAs, comm-warp specialized (validated R12),
// now with FOUR interleaved groups of 2 rows (chain hides under 3 other
// groups' compute) and the Wh slice REGISTER-RESIDENT per thread (loaded
// once, reused 512 steps; per-group LDS = h only).
// Named barrier ids: group G phase p -> 1 + G*2 + p (ids 1..8).
// mbarriers: (G*2+p), count 8, ping-pong per group.
// ---------------------------------------------------------------------------
__global__ __launch_bounds__(RT, 1) __cluster_dims__(CL, 1, 1)
void rnn_kernel(const float* __restrict__ Wh, float* __restrict__ out)
{
    extern __shared__ float sm[];
    float* sWh  = sm;                          // [64][512]           128 KB
    float* hbuf = sm + JC * HDIM;              // [NGR][2][GR][512]    32 KB
    u64*   mbar = (u64*)(hbuf + NGR * 2 * GR * HDIM);   // [NGR*2]

    const int tid  = threadIdx.x;
    const int w    = tid >> 5;          // 0..7 compute, 8 comm
    const int lane = tid & 31;
    uint32_t rank;
    asm("mov.u32 %0, %%cluster_ctarank;" : "=r"(rank));
    const int gbase = (blockIdx.x / CL) * 8;

    const uint32_t mb_base = smem_u32(mbar);
    if (tid == 0) {
#pragma unroll
        for (int i = 0; i < NGR * 2; i++) mbar_init(mb_base + i * 8, CL);
    }
    {   // load Wh rows [rank*JC, +JC) once (all 9 warps help)
        const float4* src = (const float4*)(Wh + (size_t)rank * JC * HDIM);
        float4* dst = (float4*)sWh;
        for (int i = tid; i < JC * HDIM / 4; i += RT) dst[i] = src[i];
    }
    __syncthreads();
    CLUSTER_SYNC();   // peers' mbarriers live before any arrive

    // ======================= comm warp =======================
    if (w == NCW) {
        const uint32_t my_peer_mb = (lane < CL)
            ? mapa_u32(mb_base, (rank + lane) & (CL - 1)) : 0u;
        for (int t = 1; t < SEQ; t++) {
            const int bcur = t & 1;
#pragma unroll
            for (int G = 0; G < NGR; G++) {
                nbar_sync(1 + G * 2 + bcur);
                if (lane < CL) {
                    fence_cluster();   // drain CTA's DSMEM pushes for this group
                    mbar_arrive_remote(my_peer_mb + (G * 2 + bcur) * 8);
                }
            }
        }
        return;
    }

    // ======================= compute warps =======================
    const int o   = lane & 15;          // this lane's output after butterfly
    const int b   = o >> 3;             // row in group (0..1)
    const int jj  = o & 7;
    const int ojl = rank * JC + w * 8 + jj;   // global j index

    // register-resident Wh slice: wrg[j][d*2+h] covers k = d*128 + lane*4 (+2h)
    const ulonglong2* wv2 = (const ulonglong2*)sWh + (w * 8) * (HDIM / 4) + lane;
    u64 wrg[8][8];
#pragma unroll
    for (int j = 0; j < 8; j++)
#pragma unroll
        for (int d = 0; d < 4; d++) {
            ulonglong2 v = wv2[j * (HDIM / 4) + d * 32];
            wrg[j][d * 2]     = v.x;
            wrg[j][d * 2 + 1] = v.y;
        }

    const uint32_t hb_base = smem_u32(hbuf);
    uint32_t peer_hb[CL];
#pragma unroll
    for (int r = 0; r < CL; r++)
        peer_hb[r] = mapa_u32(hb_base, (rank + r) & (CL - 1));

    int ph[NGR][2];
#pragma unroll
    for (int G = 0; G < NGR; G++) { ph[G][0] = 0; ph[G][1] = 0; }

    uint32_t obase[NGR];
    float xig[NGR];
#pragma unroll
    for (int G = 0; G < NGR; G++) {
        obase[G] = (uint32_t)((gbase + G * GR + b) * HDIM + ojl);
        xig[G] = __ldg(out + obase[G]);   // xi' = xi + bi + bh (precomputed)
    }

    for (int t = 1; t <= SEQ; t++) {
        const int bcur  = t & 1;
        const int bprev = 1 - bcur;
        const uint32_t step_off = (uint32_t)(t - 1) * (BATCH * HDIM);

#pragma unroll
        for (int G = 0; G < NGR; G++) {
            float sum = 0.f;
            if (t > 1) {
                mbar_wait_cluster(mb_base + (G * 2 + bprev) * 8, ph[G][bprev]);
                ph[G][bprev] ^= 1;
                const ulonglong2* hp = (const ulonglong2*)
                    (hbuf + (G * 2 + bprev) * GR * HDIM) + lane;

                u64 acc[GR][8];
#pragma unroll
                for (int i = 0; i < GR; i++)
#pragma unroll
                    for (int j = 0; j < 8; j++) acc[i][j] = 0ull;
#pragma unroll
                for (int d = 0; d < 4; d++) {   // k = d*128 + lane*4
                    ulonglong2 hv[GR];
#pragma unroll
                    for (int i = 0; i < GR; i++) hv[i] = hp[i * (HDIM / 4) + d * 32];
#pragma unroll
                    for (int i = 0; i < GR; i++)
#pragma unroll
                        for (int j = 0; j < 8; j++) {
                            acc[i][j] = fma2(hv[i].x, wrg[j][d * 2],     acc[i][j]);
                            acc[i][j] = fma2(hv[i].y, wrg[j][d * 2 + 1], acc[i][j]);
                        }
                }
                float v[16];
#pragma unroll
                for (int i = 0; i < GR; i++)
#pragma unroll
                    for (int j = 0; j < 8; j++) {
                        float2 a = *reinterpret_cast<float2*>(&acc[i][j]);
                        v[i * 8 + j] = a.x + a.y;
                    }
                // 4 output-split stages within 16-lane halves + xor-16 fold
#pragma unroll
                for (int m = 0; m < 4; m++) {
                    const int mb2 = (lane >> m) & 1;
#pragma unroll
                    for (int j2 = 0; j2 < (8 >> m); j2++) {
                        float send = v[2 * j2 + 1 - mb2];
                        float recv = __shfl_xor_sync(0xffffffffu, send, 1 << m);
                        v[j2] = v[2 * j2 + mb2] + recv;
                    }
                }
                v[0] += __shfl_xor_sync(0xffffffffu, v[0], 16);
                sum = v[0];
            }

            const float hval = tanhf(sum + xig[G]);
            if (t < SEQ) xig[G] = __ldg(out + step_off + BATCH * HDIM + obase[G]);

            if (t < SEQ) {
                float nxt = __shfl_down_sync(0xffffffffu, hval, 1);
                if (lane < 16 && !(lane & 1)) {   // even outputs push (jj, jj+1)
                    float2 p2 = make_float2(hval, nxt);
                    u64 pv = *reinterpret_cast<u64*>(&p2);
                    const uint32_t boff = (G * 2 + bcur) * GR * HDIM + b * HDIM + ojl;
                    *reinterpret_cast<u64*>(hbuf + boff) = pv;   // self, plain
#pragma unroll
                    for (int r = 1; r < CL; r++)
                        st_cluster_b64(peer_hb[r] + boff * 4, pv);
                }
                nbar_arrive(1 + G * 2 + bcur);   // non-blocking handoff to comm
            }
            if (lane < 16) {
                out[step_off + obase[G]] = hval;
                if (t == SEQ)
                    out[(uint32_t)SEQ * (BATCH * HDIM) + obase[G]] = hval;
            }
        }
    }
}

// ---------------------------------------------------------------------------
extern "C" void kernel_launch(void* const* d_in, const int* in_sizes, int n_in,
                              void* d_out, int out_size)
{
    const float* x  = (const float*)d_in[0];
    const float* Wi = (const float*)d_in[1];
    const float* bi = (const float*)d_in[2];
    const float* Wh = (const float*)d_in[3];
    const float* bh = (const float*)d_in[4];
    float* out = (float*)d_out;

    const int XI_SMEM  = (128 * 130 + 64 * 130) * 4;                     // 99840 B
    const int RNN_SMEM = (JC * HDIM + NGR * 2 * GR * HDIM) * 4 + 128;    // 164 KB

    cudaFuncSetAttribute(xi_kernel,  cudaFuncAttributeMaxDynamicSharedMemorySize, XI_SMEM);
    cudaFuncSetAttribute(rnn_kernel, cudaFuncAttributeMaxDynamicSharedMemorySize, RNN_SMEM);

    xi_kernel<<<dim3(32768 / 64, HDIM / 128), 256, XI_SMEM>>>(x, Wi, bi, bh, out);
    rnn_kernel<<<NCLUST * CL, RT, RNN_SMEM>>>(Wh, out);
}

// round 15
// speedup vs baseline: 1.1283x; 1.1283x over previous
#include <cuda_runtime.h>
#include <cstdint>
#include <cstddef>

#define SEQ    512
#define BATCH  64
#define INDIM  128
#define HDIM   512

#define CL     8             // CTAs per cluster (H split)
#define NCLUST 8             // clusters; each serves 8 batch rows
#define NGR    2             // interleaved groups per cluster
#define GROWS  4             // rows per group (2*4 = 8 rows)
#define JC     (HDIM / CL)   // 64 j columns per CTA
#define NCW    8             // compute warps
#define RT     (NCW * 32 + 32)   // 288: 8 compute + 1 comm warp
#define CHUNKB 1024          // bytes each CTA contributes per group-step
#define SLOTF  2048          // floats per (G,p) buffer: 8 ranks * 4 rows * 64 j

typedef unsigned long long u64;

__device__ __forceinline__ u64 fma2(u64 a, u64 b, u64 c) {
    u64 d;
    asm("fma.rn.f32x2 %0, %1, %2, %3;" : "=l"(d) : "l"(a), "l"(b), "l"(c));
    return d;
}
__device__ __forceinline__ uint32_t smem_u32(const void* p) {
    uint32_t a;
    asm("{ .reg .u64 t; cvta.to.shared.u64 t, %1; cvt.u32.u64 %0, t; }" : "=r"(a) : "l"(p));
    return a;
}
__device__ __forceinline__ uint32_t mapa_u32(uint32_t a, uint32_t r) {
    uint32_t d;
    asm("mapa.shared::cluster.u32 %0, %1, %2;" : "=r"(d) : "r"(a), "r"(r));
    return d;
}
__device__ __forceinline__ void mbar_init(uint32_t a, uint32_t cnt) {
    asm volatile("mbarrier.init.shared.b64 [%0], %1;" :: "r"(a), "r"(cnt) : "memory");
}
__device__ __forceinline__ void mbar_expect_tx(uint32_t a, uint32_t tx) {
    asm volatile("mbarrier.arrive.expect_tx.shared.b64 _, [%0], %1;"
                 :: "r"(a), "r"(tx) : "memory");
}
__device__ __forceinline__ void mbar_arrive_local(uint32_t a) {   // release.cta
    asm volatile("mbarrier.arrive.shared::cta.b64 _, [%0];" :: "r"(a) : "memory");
}
__device__ __forceinline__ void mbar_wait_cluster(uint32_t a, uint32_t parity) {
    asm volatile(
        "{\n\t"
        ".reg .pred P;\n\t"
        "WL_%=:\n\t"
        "mbarrier.try_wait.parity.acquire.cluster.shared::cta.b64 P, [%0], %1, 0x989680;\n\t"
        "@P bra.uni WD_%=;\n\t"
        "bra.uni WL_%=;\n\t"
        "WD_%=:\n\t"
        "}"
        :: "r"(a), "r"(parity) : "memory");
}
// SMEM(cta) -> SMEM(peer CTA) bulk DMA with tx-signal on the peer's mbarrier
__device__ __forceinline__ void bulk_dsmem(uint32_t dst, uint32_t src,
                                           uint32_t bytes, uint32_t mbar) {
    asm volatile(
        "cp.async.bulk.shared::cluster.shared::cta.mbarrier::complete_tx::bytes "
        "[%0], [%1], %2, [%3];"
        :: "r"(dst), "r"(src), "r"(bytes), "r"(mbar) : "memory");
}
__device__ __forceinline__ void fence_proxy_async_cta() {
    asm volatile("fence.proxy.async.shared::cta;" ::: "memory");
}
__device__ __forceinline__ void nbar_arrive(int id) {   // non-blocking
    asm volatile("bar.arrive %0, %1;" :: "r"(id), "r"(RT) : "memory");
}
__device__ __forceinline__ void nbar_sync(int id) {     // blocking (comm warp)
    asm volatile("bar.sync %0, %1;" :: "r"(id), "r"(RT) : "memory");
}
#define CLUSTER_SYNC() do { \
    asm volatile("barrier.cluster.arrive.aligned;" ::: "memory"); \
    asm volatile("barrier.cluster.wait.aligned;"   ::: "memory"); \
} while (0)

// ---------------------------------------------------------------------------
// xi kernel (validated R3-R13): out[s][b][h] = x.Wi + bi + bh
// ---------------------------------------------------------------------------
__global__ __launch_bounds__(256) void xi_kernel(
    const float* __restrict__ x, const float* __restrict__ Wi,
    const float* __restrict__ bi, const float* __restrict__ bh,
    float* __restrict__ out)
{
    extern __shared__ float sm[];
    float* ws = sm;               // [128][130]
    float* xs = sm + 128 * 130;   // [64][130]

    const int tid = threadIdx.x;
    const int sb0 = blockIdx.x * 64;
    const int h0  = blockIdx.y * 128;

    for (int i = tid; i < 128 * INDIM; i += 256) {
        int r = i >> 7, k = i & 127;
        ws[r * 130 + k] = Wi[(h0 + r) * INDIM + k];
    }
    for (int i = tid; i < 64 * INDIM; i += 256) {
        int r = i >> 7, k = i & 127;
        xs[r * 130 + k] = x[(size_t)(sb0 + r) * INDIM + k];
    }
    __syncthreads();

    const int w  = tid >> 5;
    const int tx = tid & 31;

    u64 acc2[8][4];
#pragma unroll
    for (int i = 0; i < 8; i++)
#pragma unroll
        for (int j = 0; j < 4; j++) acc2[i][j] = 0ull;

    const u64* xb2 = (const u64*)xs + (w * 8) * 65;
    const u64* wb2 = (const u64*)ws;

#pragma unroll 4
    for (int kp = 0; kp < 64; kp++) {
        u64 xv[8], wv[4];
#pragma unroll
        for (int i = 0; i < 8; i++) xv[i] = xb2[i * 65 + kp];
#pragma unroll
        for (int j = 0; j < 4; j++) wv[j] = wb2[(j * 32 + tx) * 65 + kp];
#pragma unroll
        for (int i = 0; i < 8; i++)
#pragma unroll
            for (int j = 0; j < 4; j++) acc2[i][j] = fma2(xv[i], wv[j], acc2[i][j]);
    }

#pragma unroll
    for (int j = 0; j < 4; j++) {
        int h = h0 + j * 32 + tx;
        float b = bi[h] + bh[h];
#pragma unroll
        for (int i = 0; i < 8; i++) {
            float2 a = *reinterpret_cast<float2*>(&acc2[i][j]);
            out[(size_t)(sb0 + w * 8 + i) * HDIM + h] = a.x + a.y + b;
        }
    }
}

// ---------------------------------------------------------------------------
// Recurrence: R14 design + the missing local-ordering arrive.
// mbarriers now count=2: phase completes on (a) expect_tx matched by the 7
// remote 1KB bulks AND (b) one local release-arrive from the comm warp,
// issued after its bar.sync — this orders the CTA's OWN plain-store staged
// chunk before the consumers' acquire-wait (the R14 race).
// hbuf layout: [G][p][rank][4 rows][64 j] floats.
// ---------------------------------------------------------------------------
__global__ __launch_bounds__(RT, 1) __cluster_dims__(CL, 1, 1)
void rnn_kernel(const float* __restrict__ Wh, float* __restrict__ out)
{
    extern __shared__ float sm[];
    float* sWh  = sm;                          // [64][512]          128 KB
    float* hbuf = sm + JC * HDIM;              // [2][2][SLOTF]       32 KB
    u64*   mbar = (u64*)(hbuf + NGR * 2 * SLOTF);   // [4]

    const int tid  = threadIdx.x;
    const int w    = tid >> 5;          // 0..7 compute, 8 comm
    const int lane = tid & 31;
    uint32_t rank;
    asm("mov.u32 %0, %%cluster_ctarank;" : "=r"(rank));
    const int gbase = (blockIdx.x / CL) * 8;

    const uint32_t mb_base = smem_u32(mbar);
    const uint32_t hb_base = smem_u32(hbuf);
    if (tid == 0) {
#pragma unroll
        for (int i = 0; i < NGR * 2; i++) mbar_init(mb_base + i * 8, 2);
        // expects for t=1 pushes (phase index p=1) — before CLUSTER_SYNC
        mbar_expect_tx(mb_base + (0 * 2 + 1) * 8, (CL - 1) * CHUNKB);
        mbar_expect_tx(mb_base + (1 * 2 + 1) * 8, (CL - 1) * CHUNKB);
    }
    {   // load Wh rows [rank*JC, +JC) once (all 9 warps help)
        const float4* src = (const float4*)(Wh + (size_t)rank * JC * HDIM);
        float4* dst = (float4*)sWh;
        for (int i = tid; i < JC * HDIM / 4; i += RT) dst[i] = src[i];
    }
    __syncthreads();
    CLUSTER_SYNC();   // peers' mbarriers + expects live before any bulk

    // ======================= comm warp =======================
    if (w == NCW) {
        uint32_t peer_hb[CL], peer_mbb[CL];
#pragma unroll
        for (int r = 1; r < CL; r++) {
            uint32_t pr = (rank + r) & (CL - 1);
            peer_hb[r]  = mapa_u32(hb_base, pr);
            peer_mbb[r] = mapa_u32(mb_base, pr);
        }
        for (int t = 1; t < SEQ; t++) {
            const int bcur = t & 1;
#pragma unroll
            for (int G = 0; G < NGR; G++) {
                nbar_sync(1 + G * 2 + bcur);   // orders compute staging stores
                if (lane == 0) {
                    // expect for step t+1 arrivals on the other phase buffer
                    mbar_expect_tx(mb_base + (G * 2 + (1 - bcur)) * 8,
                                   (CL - 1) * CHUNKB);
                    fence_proxy_async_cta();   // generic->async proxy order
                    const uint32_t off =
                        ((uint32_t)(G * 2 + bcur) * SLOTF + rank * 256) * 4;
                    const uint32_t src = hb_base + off;
                    const uint32_t mbo = (G * 2 + bcur) * 8;
#pragma unroll
                    for (int r = 1; r < CL; r++)
                        bulk_dsmem(peer_hb[r] + off, src, CHUNKB,
                                   peer_mbb[r] + mbo);
                    // local release-arrive: orders OWN staged chunk for
                    // this CTA's consumers (the arrive the R14 race missed)
                    mbar_arrive_local(mb_base + mbo);
                }
            }
        }
        return;
    }

    // ======================= compute warps =======================
    const int b   = lane >> 3;          // output row in group (after butterfly)
    const int jl  = lane & 7;           // local j within warp octet
    const int jw  = w * 8 + jl;         // j within CTA (0..63)
    const int ojl = rank * JC + jw;     // global j index

    const ulonglong2* wv2 = (const ulonglong2*)sWh + (w * 8) * (HDIM / 4) + lane;

    int ph[NGR][2];
#pragma unroll
    for (int G = 0; G < NGR; G++) { ph[G][0] = 0; ph[G][1] = 0; }

    uint32_t obase[NGR];
    float xig[NGR];
#pragma unroll
    for (int G = 0; G < NGR; G++) {
        obase[G] = (uint32_t)((gbase + G * GROWS + b) * HDIM + ojl);
        xig[G] = __ldg(out + obase[G]);   // xi' = xi + bi + bh (precomputed)
    }

    // h read base (ulonglong2 units): rank = 2d + (lane>>4), inner (lane&15)
    const int hp_off = (lane >> 4) * 64 + (lane & 15);

    for (int t = 1; t <= SEQ; t++) {
        const int bcur  = t & 1;
        const int bprev = 1 - bcur;
        const uint32_t step_off = (uint32_t)(t - 1) * (BATCH * HDIM);

#pragma unroll
        for (int G = 0; G < NGR; G++) {
            float sum = 0.f;
            if (t > 1) {
                mbar_wait_cluster(mb_base + (G * 2 + bprev) * 8, ph[G][bprev]);
                ph[G][bprev] ^= 1;
                const ulonglong2* hp = (const ulonglong2*)hbuf
                    + (G * 2 + bprev) * (SLOTF / 4) + hp_off;

                u64 acc[GROWS][8];
#pragma unroll
                for (int i = 0; i < GROWS; i++)
#pragma unroll
                    for (int j = 0; j < 8; j++) acc[i][j] = 0ull;
#pragma unroll
                for (int d = 0; d < 4; d++) {   // k = d*128 + lane*4
                    ulonglong2 hv[GROWS];
#pragma unroll
                    for (int i = 0; i < GROWS; i++)
                        hv[i] = hp[d * 128 + i * 16];
                    ulonglong2 wv[8];
#pragma unroll
                    for (int j = 0; j < 8; j++) wv[j] = wv2[j * (HDIM / 4) + d * 32];
#pragma unroll
                    for (int i = 0; i < GROWS; i++)
#pragma unroll
                        for (int j = 0; j < 8; j++) {
                            acc[i][j] = fma2(hv[i].x, wv[j].x, acc[i][j]);
                            acc[i][j] = fma2(hv[i].y, wv[j].y, acc[i][j]);
                        }
                }
                float v[32];
#pragma unroll
                for (int i = 0; i < GROWS; i++)
#pragma unroll
                    for (int j = 0; j < 8; j++) {
                        float2 a = *reinterpret_cast<float2*>(&acc[i][j]);
                        v[i * 8 + j] = a.x + a.y;
                    }
#pragma unroll
                for (int m = 0; m < 5; m++) {
                    const int mb2 = (lane >> m) & 1;
#pragma unroll
                    for (int j2 = 0; j2 < (16 >> m); j2++) {
                        float send = v[2 * j2 + 1 - mb2];
                        float recv = __shfl_xor_sync(0xffffffffu, send, 1 << m);
                        v[j2] = v[2 * j2 + mb2] + recv;
                    }
                }
                sum = v[0];
            }

            const float hval = tanhf(sum + xig[G]);
            if (t < SEQ) xig[G] = __ldg(out + step_off + BATCH * HDIM + obase[G]);

            if (t < SEQ) {
                // stage packed (j, j+1) into OWN rank-slot (plain local store)
                float nxt = __shfl_down_sync(0xffffffffu, hval, 1);
                if (!(lane & 1)) {
                    float2 p2 = make_float2(hval, nxt);
                    u64 pv = *reinterpret_cast<u64*>(&p2);
                    float* slot = hbuf + (G * 2 + bcur) * SLOTF
                                + (int)rank * 256 + b * 64 + jw;
                    *reinterpret_cast<u64*>(slot) = pv;
                }
                nbar_arrive(1 + G * 2 + bcur);   // non-blocking handoff to comm
            }
            out[step_off + obase[G]] = hval;
            if (t == SEQ)
                out[(uint32_t)SEQ * (BATCH * HDIM) + obase[G]] = hval;
        }
    }
}

// ---------------------------------------------------------------------------
extern "C" void kernel_launch(void* const* d_in, const int* in_sizes, int n_in,
                              void* d_out, int out_size)
{
    const float* x  = (const float*)d_in[0];
    const float* Wi = (const float*)d_in[1];
    const float* bi = (const float*)d_in[2];
    const float* Wh = (const float*)d_in[3];
    const float* bh = (const float*)d_in[4];
    float* out = (float*)d_out;

    const int XI_SMEM  = (128 * 130 + 64 * 130) * 4;                    // 99840 B
    const int RNN_SMEM = (JC * HDIM + NGR * 2 * SLOTF) * 4 + 64;        // ~164 KB

    cudaFuncSetAttribute(xi_kernel,  cudaFuncAttributeMaxDynamicSharedMemorySize, XI_SMEM);
    cudaFuncSetAttribute(rnn_kernel, cudaFuncAttributeMaxDynamicSharedMemorySize, RNN_SMEM);

    xi_kernel<<<dim3(32768 / 64, HDIM / 128), 256, XI_SMEM>>>(x, Wi, bi, bh, out);
    rnn_kernel<<<NCLUST * CL, RT, RNN_SMEM>>>(Wh, out);
}